// round 3
// baseline (speedup 1.0000x reference)
#include <cuda_runtime.h>
#include <cuda_bf16.h>
#include <cstdint>

// ============================================================================
// Supervised contrastive loss, B=8192, D=256, NUM_CLASSES=100, T=0.07
//
// K0 k_prep : label width detect + convert, class bucketing (counts/offsets/
//             index lists), zero accumulators
// K1 k_cvt  : z fp32 -> bf16 (vectorized)
// K2 k_gemm : SYMMETRIC fused bf16 GEMM (triangular block grid): exp + mask +
//             row-sums AND col-sums -> g_sumneg  (half the MMAs + half the exps)
// K3 k_posloss : per-class clique; each unordered positive pair computed once
//             from smem-resident bf16 vectors; lane-parallel log1p/exp
// K4 k_fin  : finalize scalar
// ============================================================================

#define B_N   8192
#define D_K   256
#define NCLS  100
#define INV_T 14.285714285714285714f  // 1 / 0.07

// ---- scratch (static device memory; no allocations anywhere) ----
__device__ __nv_bfloat16 g_zb[B_N * D_K];   // 4 MB bf16 copy of z
__device__ int           g_lab[B_N];
__device__ float         g_sumneg[B_N];
__device__ int           g_cls_off[NCLS + 1];
__device__ int           g_cls_idx[B_N];
__device__ float         g_loss_sum;
__device__ int           g_valid;

// ============================================================================
// K0: prep — labels, class buckets, zero accumulators
// ============================================================================
__global__ void k_prep(const void* lab_raw) {
    __shared__ int s_nonzero;
    __shared__ int s_cnt[NCLS];
    __shared__ int s_off[NCLS];
    __shared__ int s_fill[NCLS];

    const int t = threadIdx.x;
    if (t == 0) s_nonzero = 0;
    for (int c = t; c < NCLS; c += blockDim.x) { s_cnt[c] = 0; s_fill[c] = 0; }
    __syncthreads();

    const int* p32 = (const int*)lab_raw;
    // int64 LE labels in [0,100): every odd 32-bit word is 0. For int32 random
    // labels, 4096 words all-zero is impossible.
    int local = 0;
    for (int i = t; i < B_N / 2; i += blockDim.x)
        if (p32[2 * i + 1] != 0) local = 1;
    if (local) atomicOr(&s_nonzero, 1);
    __syncthreads();
    const bool is64 = (s_nonzero == 0);

    for (int i = t; i < B_N; i += blockDim.x) {
        int l = is64 ? p32[2 * i] : p32[i];
        g_lab[i]    = l;
        g_sumneg[i] = 0.f;
        atomicAdd(&s_cnt[l], 1);
    }
    if (t == 0) { g_loss_sum = 0.f; g_valid = 0; }
    __syncthreads();

    if (t == 0) {
        int acc = 0;
        for (int c = 0; c < NCLS; c++) {
            s_off[c] = acc;
            g_cls_off[c] = acc;
            acc += s_cnt[c];
        }
        g_cls_off[NCLS] = acc;
    }
    __syncthreads();

    for (int i = t; i < B_N; i += blockDim.x) {
        int l = g_lab[i];
        int pos = s_off[l] + atomicAdd(&s_fill[l], 1);
        g_cls_idx[pos] = i;
    }
}

// ============================================================================
// K1: fp32 -> bf16 (vectorized: float4 -> 2x bf16x2)
// ============================================================================
__global__ void k_cvt(const float* __restrict__ z) {
    int i = blockIdx.x * blockDim.x + threadIdx.x;   // over (B_N*D_K)/4
    float4 v = ((const float4*)z)[i];
    __nv_bfloat162* o = (__nv_bfloat162*)g_zb;
    o[2 * i]     = __floats2bfloat162_rn(v.x, v.y);
    o[2 * i + 1] = __floats2bfloat162_rn(v.z, v.w);
}

// ============================================================================
// K2: symmetric fused GEMM + exp + mask + row/col sums
// ============================================================================
#define BM   128
#define BN   128
#define BK   32
#define NBLK (B_N / BM)   // 64
#define LDT  40           // padded smem stride: conflict-free ldmatrix

__device__ __forceinline__ void cp16(uint32_t dst, const void* src) {
    asm volatile("cp.async.cg.shared.global [%0], [%1], 16;\n" :: "r"(dst), "l"(src));
}

__device__ __forceinline__ void mma16816(float* c, const uint32_t* a, const uint32_t* b) {
    asm volatile(
        "mma.sync.aligned.m16n8k16.row.col.f32.bf16.bf16.f32 "
        "{%0,%1,%2,%3}, {%4,%5,%6,%7}, {%8,%9}, {%0,%1,%2,%3};"
        : "+f"(c[0]), "+f"(c[1]), "+f"(c[2]), "+f"(c[3])
        : "r"(a[0]), "r"(a[1]), "r"(a[2]), "r"(a[3]), "r"(b[0]), "r"(b[1]));
}

__global__ __launch_bounds__(256, 2) void k_gemm() {
    __shared__ __align__(16) __nv_bfloat16 sA[2][BM * LDT];
    __shared__ __align__(16) __nv_bfloat16 sB[2][BN * LDT];
    __shared__ int   s_rlab[BM];
    __shared__ int   s_clab[BN];
    __shared__ float s_rows[BM];
    __shared__ float s_cols[BN];

    const int t    = threadIdx.x;
    const int warp = t >> 5;
    const int lane = t & 31;
    const int wm   = warp >> 2;   // 0..1
    const int wn   = warp & 3;    // 0..3

    // triangular decode: bid -> (bi, bj), bj >= bi
    int bi = 0, rem = blockIdx.x;
    #pragma unroll 1
    while (rem >= NBLK - bi) { rem -= NBLK - bi; bi++; }
    const int  bj   = bi + rem;
    const bool diag = (bi == bj);
    const int iBase = bi * BM;
    const int jBase = bj * BN;

    if (t < BM) {
        s_rlab[t] = g_lab[iBase + t];
        s_clab[t] = g_lab[jBase + t];
        s_rows[t] = 0.f;
        s_cols[t] = 0.f;
    }

    const __nv_bfloat16* gA = g_zb + (size_t)iBase * D_K;
    const __nv_bfloat16* gB = g_zb + (size_t)jBase * D_K;

    uint32_t aS[2], bS[2];
    aS[0] = (uint32_t)__cvta_generic_to_shared(&sA[0][0]);
    aS[1] = (uint32_t)__cvta_generic_to_shared(&sA[1][0]);
    bS[0] = (uint32_t)__cvta_generic_to_shared(&sB[0][0]);
    bS[1] = (uint32_t)__cvta_generic_to_shared(&sB[1][0]);

    float acc[4][4][4];
    #pragma unroll
    for (int a = 0; a < 4; a++)
        #pragma unroll
        for (int b = 0; b < 4; b++)
            #pragma unroll
            for (int r = 0; r < 4; r++) acc[a][b][r] = 0.f;

    auto load_stage = [&](int st, int kt) {
        int k0 = kt * BK;
        #pragma unroll
        for (int rep = 0; rep < 2; rep++) {
            int c   = t + rep * 256;
            int row = c >> 2;
            int cc  = c & 3;
            uint32_t so = (uint32_t)(row * LDT + cc * 8) * 2u;
            size_t   go = (size_t)row * D_K + k0 + cc * 8;
            cp16(aS[st] + so, gA + go);
            cp16(bS[st] + so, gB + go);
        }
    };

    load_stage(0, 0);
    asm volatile("cp.async.commit_group;\n" ::);

    const int NKT = D_K / BK;   // 8
    for (int kt = 0; kt < NKT; kt++) {
        int cur = kt & 1;
        asm volatile("cp.async.wait_group 0;\n" ::);
        __syncthreads();
        if (kt + 1 < NKT) {
            load_stage((kt + 1) & 1, kt + 1);
            asm volatile("cp.async.commit_group;\n" ::);
        }

        #pragma unroll
        for (int ks = 0; ks < 2; ks++) {
            const int k0 = ks * 16;
            uint32_t af[4][4], bf[4][2];
            #pragma unroll
            for (int mi = 0; mi < 4; mi++) {
                int r = wm * 64 + mi * 16 + (lane & 15);
                int c = k0 + ((lane >> 4) << 3);
                uint32_t addr = aS[cur] + (uint32_t)(r * LDT + c) * 2u;
                asm volatile(
                    "ldmatrix.sync.aligned.m8n8.x4.shared.b16 {%0,%1,%2,%3}, [%4];"
                    : "=r"(af[mi][0]), "=r"(af[mi][1]), "=r"(af[mi][2]), "=r"(af[mi][3])
                    : "r"(addr));
            }
            #pragma unroll
            for (int ni = 0; ni < 4; ni++) {
                int l = lane & 15;
                int r = wn * 32 + ni * 8 + (l & 7);
                int c = k0 + ((l >> 3) << 3);
                uint32_t addr = bS[cur] + (uint32_t)(r * LDT + c) * 2u;
                asm volatile(
                    "ldmatrix.sync.aligned.m8n8.x2.shared.b16 {%0,%1}, [%2];"
                    : "=r"(bf[ni][0]), "=r"(bf[ni][1])
                    : "r"(addr));
            }
            #pragma unroll
            for (int mi = 0; mi < 4; mi++)
                #pragma unroll
                for (int ni = 0; ni < 4; ni++)
                    mma16816(acc[mi][ni], af[mi], bf[ni]);
        }
        __syncthreads();
    }

    // ---- epilogue: exp + mask; row sums always, col sums when off-diagonal ----
    const int qrow = lane >> 2;        // 0..7
    const int qcol = (lane & 3) * 2;   // 0,2,4,6

    #pragma unroll
    for (int mi = 0; mi < 4; mi++) {
        int r0  = wm * 64 + mi * 16 + qrow;
        int lr0 = s_rlab[r0];
        int lr1 = s_rlab[r0 + 8];
        float s0 = 0.f, s1 = 0.f;
        #pragma unroll
        for (int ni = 0; ni < 4; ni++) {
            int c0  = wn * 32 + ni * 8 + qcol;
            int lc0 = s_clab[c0];
            int lc1 = s_clab[c0 + 1];
            float e00 = (lr0 != lc0) ? __expf(acc[mi][ni][0] * INV_T) : 0.f;
            float e01 = (lr0 != lc1) ? __expf(acc[mi][ni][1] * INV_T) : 0.f;
            float e10 = (lr1 != lc0) ? __expf(acc[mi][ni][2] * INV_T) : 0.f;
            float e11 = (lr1 != lc1) ? __expf(acc[mi][ni][3] * INV_T) : 0.f;
            s0 += e00 + e01;
            s1 += e10 + e11;
            if (!diag) {
                // column sums over the 16 rows this warp-tile covers
                float cs0 = e00 + e10;
                float cs1 = e01 + e11;
                #pragma unroll
                for (int o = 4; o <= 16; o <<= 1) {
                    cs0 += __shfl_xor_sync(0xffffffffu, cs0, o);
                    cs1 += __shfl_xor_sync(0xffffffffu, cs1, o);
                }
                if (lane < 4) {
                    atomicAdd(&s_cols[c0],     cs0);
                    atomicAdd(&s_cols[c0 + 1], cs1);
                }
            }
        }
        s0 += __shfl_xor_sync(0xffffffffu, s0, 1);
        s0 += __shfl_xor_sync(0xffffffffu, s0, 2);
        s1 += __shfl_xor_sync(0xffffffffu, s1, 1);
        s1 += __shfl_xor_sync(0xffffffffu, s1, 2);
        if ((lane & 3) == 0) {
            atomicAdd(&s_rows[r0],     s0);
            atomicAdd(&s_rows[r0 + 8], s1);
        }
    }
    __syncthreads();
    if (t < BM) {
        atomicAdd(&g_sumneg[iBase + t], s_rows[t]);
        if (!diag) atomicAdd(&g_sumneg[jBase + t], s_cols[t]);
    }
}

// ============================================================================
// K3: per-class positive cliques, each unordered pair once
// ============================================================================
#define CAP_V 256    // max class size held in smem as bf16 vectors (128 KB)
#define CAP_R 1024   // max class size for per-row arrays (never approached)
#define SMEM_POS (CAP_V * D_K * 2 + CAP_R * (4 + 4 + 4))

__global__ __launch_bounds__(256) void k_posloss() {
    extern __shared__ char dyn[];
    __nv_bfloat16* sv   = (__nv_bfloat16*)dyn;                 // CAP_V * 256
    float*         s_sn = (float*)(dyn + CAP_V * D_K * 2);
    float*         s_rl = s_sn + CAP_R;
    int*           s_idx = (int*)(s_rl + CAP_R);
    __shared__ float s_w[8];

    const int c   = blockIdx.x;
    const int off = g_cls_off[c];
    int n = g_cls_off[c + 1] - off;
    if (n < 2) return;
    if (n > CAP_R) n = CAP_R;   // unreachable safety clamp

    const int t = threadIdx.x, warp = t >> 5, lane = t & 31;

    for (int m = t; m < n; m += 256) {
        int idx = g_cls_idx[off + m];
        s_idx[m] = idx;
        s_sn[m]  = g_sumneg[idx];
        s_rl[m]  = 0.f;
    }
    __syncthreads();

    const bool vsm = (n <= CAP_V);
    if (vsm) {
        for (int w = t; w < n * (D_K / 2); w += 256) {
            int m = w >> 7, p = w & 127;
            ((uint32_t*)sv)[m * (D_K / 2) + p] =
                ((const uint32_t*)(g_zb + (size_t)s_idx[m] * D_K))[p];
        }
    }
    __syncthreads();

    for (int i = warp; i < n; i += 8) {
        const uint32_t* vi = vsm ? (const uint32_t*)(sv + (size_t)i * D_K)
                                 : (const uint32_t*)(g_zb + (size_t)s_idx[i] * D_K);
        float zi[8];
        #pragma unroll
        for (int e = 0; e < 4; e++) {
            uint32_t p = vi[lane + 32 * e];
            float2 f = __bfloat1622float2(*(__nv_bfloat162*)&p);
            zi[2 * e] = f.x; zi[2 * e + 1] = f.y;
        }
        const float sni = s_sn[i];
        float accl = 0.f;

        for (int jb = i + 1; jb < n; jb += 32) {
            int chunk = min(32, n - jb);
            float dmine = 0.f;
            for (int u = 0; u < chunk; u++) {
                const int j = jb + u;
                const uint32_t* vj = vsm ? (const uint32_t*)(sv + (size_t)j * D_K)
                                         : (const uint32_t*)(g_zb + (size_t)s_idx[j] * D_K);
                float d = 0.f;
                #pragma unroll
                for (int e = 0; e < 4; e++) {
                    uint32_t p = vj[lane + 32 * e];
                    float2 f = __bfloat1622float2(*(__nv_bfloat162*)&p);
                    d += zi[2 * e] * f.x + zi[2 * e + 1] * f.y;
                }
                #pragma unroll
                for (int o = 16; o; o >>= 1)
                    d += __shfl_xor_sync(0xffffffffu, d, o);
                if (lane == u) dmine = d;
            }
            if (lane < chunk) {
                int j = jb + lane;
                float einv = __expf(-dmine * INV_T);   // 1/e_ij
                atomicAdd(&s_rl[j], log1pf(s_sn[j] * einv));
                accl += log1pf(sni * einv);
            }
        }
        #pragma unroll
        for (int o = 16; o; o >>= 1)
            accl += __shfl_xor_sync(0xffffffffu, accl, o);
        if (lane == 0) atomicAdd(&s_rl[i], accl);
    }
    __syncthreads();

    const float inv = 1.f / (float)(n - 1);
    float part = 0.f;
    for (int m = t; m < n; m += 256) part += s_rl[m] * inv;
    #pragma unroll
    for (int o = 16; o; o >>= 1)
        part += __shfl_xor_sync(0xffffffffu, part, o);
    if (lane == 0) s_w[warp] = part;
    __syncthreads();
    if (t == 0) {
        float tot = 0.f;
        #pragma unroll
        for (int w = 0; w < 8; w++) tot += s_w[w];
        atomicAdd(&g_loss_sum, tot);
        atomicAdd(&g_valid, n);
    }
}

// ============================================================================
// K4: finalize
// ============================================================================
__global__ void k_fin(float* out) {
    out[0] = (g_valid > 0) ? g_loss_sum / (float)g_valid : 0.f;
}

// ============================================================================
// launch
// ============================================================================
extern "C" void kernel_launch(void* const* d_in, const int* in_sizes, int n_in,
                              void* d_out, int out_size) {
    const float* z   = (const float*)d_in[0];
    const void*  lab = d_in[1];

    cudaFuncSetAttribute(k_posloss, cudaFuncAttributeMaxDynamicSharedMemorySize,
                         SMEM_POS);

    k_prep<<<1, 1024>>>(lab);
    k_cvt<<<(B_N * D_K / 4 + 255) / 256, 256>>>(z);
    k_gemm<<<NBLK * (NBLK + 1) / 2, 256>>>();
    k_posloss<<<NCLS, 256, SMEM_POS>>>();
    k_fin<<<1, 1>>>((float*)d_out);
}